// round 1
// baseline (speedup 1.0000x reference)
#include <cuda_runtime.h>
#include <math.h>

#define N_DST   20000
#define N_EDGE  200000
#define N_TOT   220000
#define DIM     128
#define HD      256

// ---------------- scratch (device globals; allocation-free) ----------------
__device__ float    g_src_feat[N_TOT * DIM];     // mobius_add(hyper, time_feat)
__device__ float    g_rx[N_TOT];                 // artanh(||src_feat||)/||src_feat||
__device__ float    g_feat_src[N_TOT * HD];
__device__ float    g_el[N_TOT * HD];            // logmap0(feat_src)
__device__ float    g_feat_dst[N_DST * HD];
__device__ float    g_x2[N_TOT];                 // ||feat_src||^2
__device__ float    g_y2[N_DST];                 // ||feat_dst||^2
__device__ float    g_qs[N_TOT * 2];             // dot(el, attn) per head
__device__ float    g_qr[N_DST * 2];             // dot(er, attn) per head
__device__ float    g_wsrcT[DIM * HD];           // W transposed [k][col]
__device__ float    g_wdstT[DIM * HD];
__device__ float    g_b2[2];                     // ||b_src||^2, ||b_dst||^2
__device__ float    g_e[N_EDGE * 2];
__device__ float    g_inv[N_EDGE];
__device__ float    g_z1[N_EDGE];
__device__ float    g_e2[N_EDGE * 2];
__device__ float    g_z2[N_EDGE * 2];
__device__ float    g_s1[N_DST];
__device__ float    g_s2[N_DST * 2];
__device__ unsigned g_m1[N_DST];
__device__ unsigned g_m2[N_DST * 2];

// ---------------- helpers ----------------
__device__ __forceinline__ unsigned fenc(float f) {
    unsigned u = __float_as_uint(f);
    return (u & 0x80000000u) ? ~u : (u | 0x80000000u);
}
__device__ __forceinline__ float fdec(unsigned u) {
    u = (u & 0x80000000u) ? (u & 0x7FFFFFFFu) : ~u;
    return __uint_as_float(u);
}
__device__ __forceinline__ float red16(float v) {
#pragma unroll
    for (int o = 1; o < 16; o <<= 1) v += __shfl_xor_sync(0xffffffffu, v, o);
    return v;
}
__device__ __forceinline__ float red32(float v) {
#pragma unroll
    for (int o = 16; o; o >>= 1) v += __shfl_xor_sync(0xffffffffu, v, o);
    return v;
}
// 128-thread block reduce with broadcast
__device__ __forceinline__ float blockReduce128(float v, float* sred) {
    v = red32(v);
    int w = threadIdx.x >> 5;
    __syncthreads();
    if ((threadIdx.x & 31) == 0) sred[w] = v;
    __syncthreads();
    return sred[0] + sred[1] + sred[2] + sred[3];
}

// ---------------- init ----------------
__global__ void init_kernel(float* __restrict__ out) {
    int i = blockIdx.x * blockDim.x + threadIdx.x;
    int stride = gridDim.x * blockDim.x;
    for (int j = i; j < N_DST * HD; j += stride) out[j] = 0.f;
    for (int j = i; j < N_DST; j += stride) { g_s1[j] = 0.f; g_m1[j] = 0u; }
    for (int j = i; j < 2 * N_DST; j += stride) { g_s2[j] = 0.f; g_m2[j] = 0u; }
}

__global__ void prep_w(const float* __restrict__ w_src, const float* __restrict__ w_dst) {
    int i = blockIdx.x * blockDim.x + threadIdx.x;
    if (i < DIM * HD) {
        int k = i >> 8, c = i & 255;
        g_wsrcT[i] = w_src[c * DIM + k];
        g_wdstT[i] = w_dst[c * DIM + k];
    }
}

__global__ void bias_norm(const float* __restrict__ b_src, const float* __restrict__ b_dst) {
    const float* b = blockIdx.x ? b_dst : b_src;
    float v = b[threadIdx.x];
    v = v * v;
    v = red32(v);
    __shared__ float sred[8];
    if ((threadIdx.x & 31) == 0) sred[threadIdx.x >> 5] = v;
    __syncthreads();
    if (threadIdx.x == 0) {
        float s = 0.f;
#pragma unroll
        for (int w = 0; w < 8; w++) s += sred[w];
        g_b2[blockIdx.x] = s;
    }
}

// ---------------- node prep: time feat + projx + mobius_add ----------------
__global__ void node_prep(const float* __restrict__ hyper, const float* __restrict__ dt,
                          const float* __restrict__ time_w, const float* __restrict__ time_b) {
    int node = blockIdx.x;
    int d = threadIdx.x;
    __shared__ float sred[4];
    float t = (node < N_DST) ? 0.f : dt[node - N_DST];
    float tf = cosf(fmaf(t, time_w[d], time_b[d]));
    float y2 = blockReduce128(tf * tf, sred);
    float n = sqrtf(fmaxf(y2, 1e-30f));
    if (n > 0.996f) {
        float sc = 0.996f / n;
        tf *= sc;
        y2 = y2 * sc * sc;
    }
    float x = hyper[(size_t)node * DIM + d];
    float x2 = blockReduce128(x * x, sred);
    float xy = blockReduce128(x * tf, sred);
    float num = (1.f + 2.f * xy + y2) * x + (1.f - x2) * tf;
    float den = fmaxf(1.f + 2.f * xy + x2 * y2, 1e-15f);
    float sf = num / den;
    g_src_feat[(size_t)node * DIM + d] = sf;
    float xn2 = blockReduce128(sf * sf, sred);
    if (d == 0) {
        float xn = sqrtf(fmaxf(xn2, 1e-30f));
        g_rx[node] = atanhf(fminf(xn, 0.9999999f)) / xn;
    }
}

// ---------------- GEMM (64 rows x 256 cols, K=128) + full epilogue ----------------
// epilogue: mobius_matvec scale -> mobius_add(bias) -> logmap0 -> attn dots
__global__ void gemm_epi(const float* __restrict__ bias, const float* __restrict__ attn,
                         int nrows, int is_dst) {
    extern __shared__ float sm[];
    float* Ws = sm;                 // [128][256]
    float* As = sm + DIM * HD;      // [64][128]
    const float* WT = is_dst ? g_wdstT : g_wsrcT;
    float* feat_out = is_dst ? g_feat_dst : g_feat_src;
    float* n2_out = is_dst ? g_y2 : g_x2;
    float* q_out = is_dst ? g_qr : g_qs;
    float* el_out = is_dst ? (float*)0 : g_el;

    int tid = threadIdx.x;
    int row0 = blockIdx.x * 64;

    for (int i = tid; i < (DIM * HD) / 4; i += 256)
        ((float4*)Ws)[i] = ((const float4*)WT)[i];
    for (int i = tid; i < (64 * DIM) / 4; i += 256) {
        int r = i >> 5;
        int gr = row0 + r;
        float4 v = make_float4(0.f, 0.f, 0.f, 0.f);
        if (gr < nrows) v = ((const float4*)g_src_feat)[(size_t)gr * 32 + (i & 31)];
        ((float4*)As)[i] = v;
    }
    __syncthreads();

    int ty = tid >> 4, tx = tid & 15;
    float acc[4][16];
#pragma unroll
    for (int r = 0; r < 4; r++)
#pragma unroll
        for (int i = 0; i < 16; i++) acc[r][i] = 0.f;

    const float* a_base = As + (ty * 4) * DIM;
#pragma unroll 4
    for (int k = 0; k < 128; ++k) {
        float a0 = a_base[k];
        float a1 = a_base[128 + k];
        float a2 = a_base[256 + k];
        float a3 = a_base[384 + k];
        const float* wr = Ws + k * 256 + tx * 4;
#pragma unroll
        for (int j = 0; j < 4; ++j) {
            float4 b = *(const float4*)(wr + j * 64);
            float bj[4] = {b.x, b.y, b.z, b.w};
#pragma unroll
            for (int c = 0; c < 4; c++) {
                acc[0][j * 4 + c] = fmaf(a0, bj[c], acc[0][j * 4 + c]);
                acc[1][j * 4 + c] = fmaf(a1, bj[c], acc[1][j * 4 + c]);
                acc[2][j * 4 + c] = fmaf(a2, bj[c], acc[2][j * 4 + c]);
                acc[3][j * 4 + c] = fmaf(a3, bj[c], acc[3][j * 4 + c]);
            }
        }
    }

    float bb[16], at[16];
#pragma unroll
    for (int j = 0; j < 4; j++) {
        float4 b4 = *(const float4*)(bias + j * 64 + tx * 4);
        float4 a4 = *(const float4*)(attn + j * 64 + tx * 4);
        bb[j * 4 + 0] = b4.x; bb[j * 4 + 1] = b4.y; bb[j * 4 + 2] = b4.z; bb[j * 4 + 3] = b4.w;
        at[j * 4 + 0] = a4.x; at[j * 4 + 1] = a4.y; at[j * 4 + 2] = a4.z; at[j * 4 + 3] = a4.w;
    }
    float b2v = g_b2[is_dst];

#pragma unroll 1
    for (int r = 0; r < 4; r++) {
        int row = row0 + ty * 4 + r;
        float s = 0.f;
#pragma unroll
        for (int i = 0; i < 16; i++) s += acc[r][i] * acc[r][i];
        s = red16(s);
        float mxn = sqrtf(fmaxf(s, 1e-30f));
        float rxv = (row < nrows) ? g_rx[row] : 0.f;
        float sc = tanhf(mxn * rxv) / mxn;
        float mv[16];
        float xy = 0.f;
#pragma unroll
        for (int i = 0; i < 16; i++) {
            mv[i] = acc[r][i] * sc;
            xy += mv[i] * bb[i];
        }
        xy = red16(xy);
        float x2v = sc * sc * s;
        float c1 = 1.f + 2.f * xy + b2v;
        float c2 = 1.f - x2v;
        float iden = 1.f / fmaxf(1.f + 2.f * xy + x2v * b2v, 1e-15f);
        float ftv[16];
        float fn2 = 0.f;
#pragma unroll
        for (int i = 0; i < 16; i++) {
            ftv[i] = (c1 * mv[i] + c2 * bb[i]) * iden;
            fn2 += ftv[i] * ftv[i];
        }
        fn2 = red16(fn2);
        float yn = sqrtf(fmaxf(fn2, 1e-30f));
        float lm = atanhf(fminf(yn, 0.9999999f)) / yn;
        float q0 = 0.f, q1 = 0.f;
        float elv[16];
#pragma unroll
        for (int i = 0; i < 16; i++) {
            elv[i] = lm * ftv[i];
            if (i < 8) q0 += elv[i] * at[i];
            else       q1 += elv[i] * at[i];
        }
        q0 = red16(q0);
        q1 = red16(q1);
        if (row < nrows) {
#pragma unroll
            for (int j = 0; j < 4; j++) {
                *(float4*)&feat_out[(size_t)row * HD + j * 64 + tx * 4] =
                    make_float4(ftv[j * 4 + 0], ftv[j * 4 + 1], ftv[j * 4 + 2], ftv[j * 4 + 3]);
            }
            if (el_out) {
#pragma unroll
                for (int j = 0; j < 4; j++) {
                    *(float4*)&el_out[(size_t)row * HD + j * 64 + tx * 4] =
                        make_float4(elv[j * 4 + 0], elv[j * 4 + 1], elv[j * 4 + 2], elv[j * 4 + 3]);
                }
            }
            if (tx == 0) {
                n2_out[row] = fn2;
                q_out[row * 2 + 0] = q0;
                q_out[row * 2 + 1] = q1;
            }
        }
    }
}

// ---------------- edge pass A: dot / ball_dist / e logits / segment max(inv) ----------------
__global__ void edgeA(const int* __restrict__ src_idx, const int* __restrict__ dst_idx) {
    int gid = blockIdx.x * blockDim.x + threadIdx.x;
    int e = gid >> 5, lane = gid & 31;
    if (e >= N_EDGE) return;
    int s = src_idx[e], t = dst_idx[e];
    const float4* fs = (const float4*)(g_feat_src + (size_t)s * HD);
    const float4* fd = (const float4*)(g_feat_dst + (size_t)t * HD);
    float4 a0 = fs[lane], b0 = fd[lane];
    float4 a1 = fs[lane + 32], b1 = fd[lane + 32];
    float xy = a0.x * b0.x + a0.y * b0.y + a0.z * b0.z + a0.w * b0.w +
               a1.x * b1.x + a1.y * b1.y + a1.z * b1.z + a1.w * b1.w;
    xy = red32(xy);
    if (lane == 0) {
        float x2 = g_x2[s], y2 = g_y2[t];
        float A = 1.f - 2.f * xy + y2;
        float B = 1.f - x2;
        float num2 = A * A * x2 - 2.f * A * B * xy + B * B * y2;
        float den = fmaxf(1.f - 2.f * xy + x2 * y2, 1e-15f);
        float nn = sqrtf(fmaxf(num2 / (den * den), 1e-30f));
        float dist = 2.f * atanhf(fminf(nn, 0.9999999f));
        float inv = 1.f / (1e-15f + dist);
        g_inv[e] = inv;
        g_e[e * 2 + 0] = g_qs[s * 2 + 0] + g_qr[t * 2 + 0];
        g_e[e * 2 + 1] = g_qs[s * 2 + 1] + g_qr[t * 2 + 1];
        atomicMax(&g_m1[t], fenc(inv));
    }
}

// ---------------- edge pass B: z1 = exp(inv - m1), segment sum ----------------
__global__ void edgeB(const int* __restrict__ dst_idx) {
    int e = blockIdx.x * blockDim.x + threadIdx.x;
    if (e >= N_EDGE) return;
    int t = dst_idx[e];
    float z = expf(g_inv[e] - fdec(g_m1[t]));
    g_z1[e] = z;
    atomicAdd(&g_s1[t], z);
}

// ---------------- edge pass C: dsm, leaky_relu(e*dsm), segment max ----------------
__global__ void edgeC(const int* __restrict__ dst_idx) {
    int e = blockIdx.x * blockDim.x + threadIdx.x;
    if (e >= N_EDGE) return;
    int t = dst_idx[e];
    float dsm = g_z1[e] / g_s1[t];
#pragma unroll
    for (int h = 0; h < 2; h++) {
        float v = g_e[e * 2 + h] * dsm;
        v = (v > 0.f) ? v : 0.2f * v;
        g_e2[e * 2 + h] = v;
        atomicMax(&g_m2[t * 2 + h], fenc(v));
    }
}

// ---------------- edge pass D: z2 = exp(e2 - m2), segment sum ----------------
__global__ void edgeD(const int* __restrict__ dst_idx) {
    int e = blockIdx.x * blockDim.x + threadIdx.x;
    if (e >= N_EDGE) return;
    int t = dst_idx[e];
#pragma unroll
    for (int h = 0; h < 2; h++) {
        float z = expf(g_e2[e * 2 + h] - fdec(g_m2[t * 2 + h]));
        g_z2[e * 2 + h] = z;
        atomicAdd(&g_s2[t * 2 + h], z);
    }
}

// ---------------- edge pass E: ft += el[src] * a ----------------
__global__ void edgeE(const int* __restrict__ src_idx, const int* __restrict__ dst_idx,
                      float* __restrict__ out) {
    int gid = blockIdx.x * blockDim.x + threadIdx.x;
    int e = gid >> 5, lane = gid & 31;
    if (e >= N_EDGE) return;
    int s = src_idx[e], t = dst_idx[e];
    float a0 = g_z2[e * 2 + 0] / g_s2[t * 2 + 0];
    float a1 = g_z2[e * 2 + 1] / g_s2[t * 2 + 1];
    const float4* el = (const float4*)(g_el + (size_t)s * HD);
    float4 v0 = el[lane];       // cols lane*4 .. +3    (head 0)
    float4 v1 = el[lane + 32];  // cols 128+lane*4 ..   (head 1)
    float* o = out + (size_t)t * HD;
    atomicAdd(&o[lane * 4 + 0], v0.x * a0);
    atomicAdd(&o[lane * 4 + 1], v0.y * a0);
    atomicAdd(&o[lane * 4 + 2], v0.z * a0);
    atomicAdd(&o[lane * 4 + 3], v0.w * a0);
    atomicAdd(&o[128 + lane * 4 + 0], v1.x * a1);
    atomicAdd(&o[128 + lane * 4 + 1], v1.y * a1);
    atomicAdd(&o[128 + lane * 4 + 2], v1.z * a1);
    atomicAdd(&o[128 + lane * 4 + 3], v1.w * a1);
}

// ---------------- finalize: out = expmap0(out) in place ----------------
__global__ void finalize(float* __restrict__ out) {
    int gid = blockIdx.x * blockDim.x + threadIdx.x;
    int r = gid >> 5, lane = gid & 31;
    if (r >= N_DST) return;
    float4* o = (float4*)(out + (size_t)r * HD);
    float4 u0 = o[lane], u1 = o[lane + 32];
    float s = u0.x * u0.x + u0.y * u0.y + u0.z * u0.z + u0.w * u0.w +
              u1.x * u1.x + u1.y * u1.y + u1.z * u1.z + u1.w * u1.w;
    s = red32(s);
    float un = sqrtf(fmaxf(s, 1e-30f));
    float sc = tanhf(un) / un;
    u0.x *= sc; u0.y *= sc; u0.z *= sc; u0.w *= sc;
    u1.x *= sc; u1.y *= sc; u1.z *= sc; u1.w *= sc;
    o[lane] = u0;
    o[lane + 32] = u1;
}

// ---------------- launch ----------------
extern "C" void kernel_launch(void* const* d_in, const int* in_sizes, int n_in,
                              void* d_out, int out_size) {
    const float* hyper  = (const float*)d_in[0];
    const float* dt     = (const float*)d_in[1];
    const float* time_w = (const float*)d_in[2];
    const float* time_b = (const float*)d_in[3];
    const float* w_src  = (const float*)d_in[4];
    const float* b_src  = (const float*)d_in[5];
    const float* w_dst  = (const float*)d_in[6];
    const float* b_dst  = (const float*)d_in[7];
    const float* attn   = (const float*)d_in[8];
    const int* src_idx  = (const int*)d_in[9];
    const int* dst_idx  = (const int*)d_in[10];
    float* out = (float*)d_out;

    (void)in_sizes; (void)n_in; (void)out_size;

    init_kernel<<<1024, 256>>>(out);
    prep_w<<<(DIM * HD + 255) / 256, 256>>>(w_src, w_dst);
    bias_norm<<<2, 256>>>(b_src, b_dst);
    node_prep<<<N_TOT, 128>>>(hyper, dt, time_w, time_b);

    const int SMEM = (DIM * HD + 64 * DIM) * (int)sizeof(float);  // 160 KB
    cudaFuncSetAttribute(gemm_epi, cudaFuncAttributeMaxDynamicSharedMemorySize, SMEM);
    gemm_epi<<<(N_TOT + 63) / 64, 256, SMEM>>>(b_src, attn, N_TOT, 0);
    gemm_epi<<<(N_DST + 63) / 64, 256, SMEM>>>(b_dst, attn, N_DST, 1);

    int eb = (N_EDGE * 32 + 255) / 256;   // warp-per-edge kernels
    int sb = (N_EDGE + 255) / 256;        // thread-per-edge kernels
    edgeA<<<eb, 256>>>(src_idx, dst_idx);
    edgeB<<<sb, 256>>>(dst_idx);
    edgeC<<<sb, 256>>>(dst_idx);
    edgeD<<<sb, 256>>>(dst_idx);
    edgeE<<<eb, 256>>>(src_idx, dst_idx, out);
    finalize<<<(N_DST * 32 + 255) / 256, 256>>>(out);
}

// round 2
// speedup vs baseline: 1.6845x; 1.6845x over previous
#include <cuda_runtime.h>
#include <math.h>

#define N_DST   20000
#define N_EDGE  200000
#define N_TOT   220000
#define DIM     128
#define HD      256

typedef unsigned long long u64;

// ---------------- scratch (device globals; allocation-free) ----------------
__device__ float    g_src_feat[N_TOT * DIM];     // mobius_add(hyper, time_feat)
__device__ float    g_rx[N_TOT];                 // artanh(||src_feat||)/||src_feat||
__device__ float    g_feat_src[N_TOT * HD];
__device__ float    g_el[N_TOT * HD];            // logmap0(feat_src)
__device__ float    g_feat_dst[N_DST * HD];
__device__ float    g_x2[N_TOT];                 // ||feat_src||^2
__device__ float    g_y2[N_DST];                 // ||feat_dst||^2
__device__ float    g_qs[N_TOT * 2];             // dot(el, attn) per head
__device__ float    g_qr[N_DST * 2];             // dot(er, attn) per head
__device__ float    g_wsrcT[DIM * HD];           // W transposed [k][col]
__device__ float    g_wdstT[DIM * HD];
__device__ float    g_b2[2];                     // ||b_src||^2, ||b_dst||^2
__device__ float    g_e[N_EDGE * 2];
__device__ float    g_inv[N_EDGE];
__device__ float    g_z1[N_EDGE];
__device__ float    g_e2[N_EDGE * 2];
__device__ float    g_z2[N_EDGE * 2];
__device__ float    g_s1[N_DST];
__device__ float    g_s2[N_DST * 2];
__device__ unsigned g_m1[N_DST];
__device__ unsigned g_m2[N_DST * 2];

// ---------------- helpers ----------------
__device__ __forceinline__ unsigned fenc(float f) {
    unsigned u = __float_as_uint(f);
    return (u & 0x80000000u) ? ~u : (u | 0x80000000u);
}
__device__ __forceinline__ float fdec(unsigned u) {
    u = (u & 0x80000000u) ? (u & 0x7FFFFFFFu) : ~u;
    return __uint_as_float(u);
}
__device__ __forceinline__ float red16(float v) {
#pragma unroll
    for (int o = 1; o < 16; o <<= 1) v += __shfl_xor_sync(0xffffffffu, v, o);
    return v;
}
__device__ __forceinline__ float red32(float v) {
#pragma unroll
    for (int o = 16; o; o >>= 1) v += __shfl_xor_sync(0xffffffffu, v, o);
    return v;
}
__device__ __forceinline__ u64 pack2(float lo, float hi) {
    u64 r;
    asm("mov.b64 %0, {%1, %2};" : "=l"(r) : "f"(lo), "f"(hi));
    return r;
}
__device__ __forceinline__ void unpack2(float& lo, float& hi, u64 v) {
    asm("mov.b64 {%0, %1}, %2;" : "=f"(lo), "=f"(hi) : "l"(v));
}
__device__ __forceinline__ u64 fma2(u64 a, u64 b, u64 c) {
    u64 d;
    asm("fma.rn.f32x2 %0, %1, %2, %3;" : "=l"(d) : "l"(a), "l"(b), "l"(c));
    return d;
}

// ---------------- init ----------------
__global__ void init_kernel(float* __restrict__ out) {
    int i = blockIdx.x * blockDim.x + threadIdx.x;
    int stride = gridDim.x * blockDim.x;
    for (int j = i; j < N_DST * HD / 4; j += stride) ((float4*)out)[j] = make_float4(0.f, 0.f, 0.f, 0.f);
    for (int j = i; j < N_DST; j += stride) { g_s1[j] = 0.f; g_m1[j] = 0u; }
    for (int j = i; j < 2 * N_DST; j += stride) { g_s2[j] = 0.f; g_m2[j] = 0u; }
}

__global__ void prep_w(const float* __restrict__ w_src, const float* __restrict__ w_dst) {
    int i = blockIdx.x * blockDim.x + threadIdx.x;
    if (i < DIM * HD) {
        int k = i >> 8, c = i & 255;
        g_wsrcT[i] = w_src[c * DIM + k];
        g_wdstT[i] = w_dst[c * DIM + k];
    }
}

__global__ void bias_norm(const float* __restrict__ b_src, const float* __restrict__ b_dst) {
    const float* b = blockIdx.x ? b_dst : b_src;
    float v = b[threadIdx.x];
    v = v * v;
    v = red32(v);
    __shared__ float sred[8];
    if ((threadIdx.x & 31) == 0) sred[threadIdx.x >> 5] = v;
    __syncthreads();
    if (threadIdx.x == 0) {
        float s = 0.f;
#pragma unroll
        for (int w = 0; w < 8; w++) s += sred[w];
        g_b2[blockIdx.x] = s;
    }
}

// ---------------- node prep: warp per node ----------------
__global__ void node_prep(const float* __restrict__ hyper, const float* __restrict__ dt,
                          const float* __restrict__ time_w, const float* __restrict__ time_b) {
    int gid = blockIdx.x * blockDim.x + threadIdx.x;
    int node = gid >> 5, lane = gid & 31;
    if (node >= N_TOT) return;
    float4 tw = ((const float4*)time_w)[lane];
    float4 tb = ((const float4*)time_b)[lane];
    float t = (node < N_DST) ? 0.f : __ldg(&dt[node - N_DST]);
    float4 tf;
    tf.x = cosf(fmaf(t, tw.x, tb.x));
    tf.y = cosf(fmaf(t, tw.y, tb.y));
    tf.z = cosf(fmaf(t, tw.z, tb.z));
    tf.w = cosf(fmaf(t, tw.w, tb.w));
    float y2 = red32(tf.x * tf.x + tf.y * tf.y + tf.z * tf.z + tf.w * tf.w);
    float n = sqrtf(fmaxf(y2, 1e-30f));
    if (n > 0.996f) {
        float sc = 0.996f / n;
        tf.x *= sc; tf.y *= sc; tf.z *= sc; tf.w *= sc;
        y2 = y2 * sc * sc;
    }
    float4 x = ((const float4*)hyper)[(size_t)node * 32 + lane];
    float x2 = red32(x.x * x.x + x.y * x.y + x.z * x.z + x.w * x.w);
    float xy = red32(x.x * tf.x + x.y * tf.y + x.z * tf.z + x.w * tf.w);
    float c1 = 1.f + 2.f * xy + y2;
    float c2 = 1.f - x2;
    float iden = 1.f / fmaxf(1.f + 2.f * xy + x2 * y2, 1e-15f);
    float4 sf;
    sf.x = (c1 * x.x + c2 * tf.x) * iden;
    sf.y = (c1 * x.y + c2 * tf.y) * iden;
    sf.z = (c1 * x.z + c2 * tf.z) * iden;
    sf.w = (c1 * x.w + c2 * tf.w) * iden;
    ((float4*)g_src_feat)[(size_t)node * 32 + lane] = sf;
    float xn2 = red32(sf.x * sf.x + sf.y * sf.y + sf.z * sf.z + sf.w * sf.w);
    if (lane == 0) {
        float xn = sqrtf(fmaxf(xn2, 1e-30f));
        g_rx[node] = atanhf(fminf(xn, 0.9999999f)) / xn;
    }
}

// ---------------- GEMM (64 rows x 256 cols, K=128), f32x2 packed FMA + epilogue -------
__global__ void gemm_epi(const float* __restrict__ bias, const float* __restrict__ attn,
                         int nrows, int is_dst) {
    extern __shared__ float sm[];
    float* Ws = sm;                 // [128][256]
    float* As = sm + DIM * HD;      // [64][128]
    const float* WT = is_dst ? g_wdstT : g_wsrcT;
    float* feat_out = is_dst ? g_feat_dst : g_feat_src;
    float* n2_out = is_dst ? g_y2 : g_x2;
    float* q_out = is_dst ? g_qr : g_qs;
    float* el_out = is_dst ? (float*)0 : g_el;

    int tid = threadIdx.x;
    int row0 = blockIdx.x * 64;

    for (int i = tid; i < (DIM * HD) / 4; i += 256)
        ((float4*)Ws)[i] = ((const float4*)WT)[i];
    for (int i = tid; i < (64 * DIM) / 4; i += 256) {
        int r = i >> 5;
        int gr = row0 + r;
        float4 v = make_float4(0.f, 0.f, 0.f, 0.f);
        if (gr < nrows) v = ((const float4*)g_src_feat)[(size_t)gr * 32 + (i & 31)];
        ((float4*)As)[i] = v;
    }
    __syncthreads();

    int ty = tid >> 4, tx = tid & 15;
    u64 acc2[4][8];
#pragma unroll
    for (int r = 0; r < 4; r++)
#pragma unroll
        for (int p = 0; p < 8; p++) acc2[r][p] = 0ull;

    const float* a_base = As + (ty * 4) * DIM;
#pragma unroll 2
    for (int k0 = 0; k0 < 128; k0 += 4) {
        float av[4][4];
#pragma unroll
        for (int r = 0; r < 4; r++) {
            float4 v = *(const float4*)(a_base + r * DIM + k0);
            av[r][0] = v.x; av[r][1] = v.y; av[r][2] = v.z; av[r][3] = v.w;
        }
#pragma unroll
        for (int kk = 0; kk < 4; kk++) {
            u64 ap0 = pack2(av[0][kk], av[0][kk]);
            u64 ap1 = pack2(av[1][kk], av[1][kk]);
            u64 ap2 = pack2(av[2][kk], av[2][kk]);
            u64 ap3 = pack2(av[3][kk], av[3][kk]);
            const ulonglong2* wr = (const ulonglong2*)(Ws + (k0 + kk) * 256 + tx * 4);
#pragma unroll
            for (int j = 0; j < 4; j++) {
                ulonglong2 w = wr[j * 16];   // j*64 floats = 16 ulonglong2
                acc2[0][j * 2 + 0] = fma2(ap0, w.x, acc2[0][j * 2 + 0]);
                acc2[0][j * 2 + 1] = fma2(ap0, w.y, acc2[0][j * 2 + 1]);
                acc2[1][j * 2 + 0] = fma2(ap1, w.x, acc2[1][j * 2 + 0]);
                acc2[1][j * 2 + 1] = fma2(ap1, w.y, acc2[1][j * 2 + 1]);
                acc2[2][j * 2 + 0] = fma2(ap2, w.x, acc2[2][j * 2 + 0]);
                acc2[2][j * 2 + 1] = fma2(ap2, w.y, acc2[2][j * 2 + 1]);
                acc2[3][j * 2 + 0] = fma2(ap3, w.x, acc2[3][j * 2 + 0]);
                acc2[3][j * 2 + 1] = fma2(ap3, w.y, acc2[3][j * 2 + 1]);
            }
        }
    }

    float bb[16], at[16];
#pragma unroll
    for (int j = 0; j < 4; j++) {
        float4 b4 = *(const float4*)(bias + j * 64 + tx * 4);
        float4 a4 = *(const float4*)(attn + j * 64 + tx * 4);
        bb[j * 4 + 0] = b4.x; bb[j * 4 + 1] = b4.y; bb[j * 4 + 2] = b4.z; bb[j * 4 + 3] = b4.w;
        at[j * 4 + 0] = a4.x; at[j * 4 + 1] = a4.y; at[j * 4 + 2] = a4.z; at[j * 4 + 3] = a4.w;
    }
    float b2v = g_b2[is_dst];

#pragma unroll 1
    for (int r = 0; r < 4; r++) {
        int row = row0 + ty * 4 + r;
        float acc[16];
#pragma unroll
        for (int j = 0; j < 4; j++) {
            unpack2(acc[j * 4 + 0], acc[j * 4 + 1], acc2[r][j * 2 + 0]);
            unpack2(acc[j * 4 + 2], acc[j * 4 + 3], acc2[r][j * 2 + 1]);
        }
        float s = 0.f;
#pragma unroll
        for (int i = 0; i < 16; i++) s += acc[i] * acc[i];
        s = red16(s);
        float mxn = sqrtf(fmaxf(s, 1e-30f));
        float rxv = (row < nrows) ? g_rx[row] : 0.f;
        float sc = tanhf(mxn * rxv) / mxn;
        float mv[16];
        float xy = 0.f;
#pragma unroll
        for (int i = 0; i < 16; i++) {
            mv[i] = acc[i] * sc;
            xy += mv[i] * bb[i];
        }
        xy = red16(xy);
        float x2v = sc * sc * s;
        float c1 = 1.f + 2.f * xy + b2v;
        float c2 = 1.f - x2v;
        float iden = 1.f / fmaxf(1.f + 2.f * xy + x2v * b2v, 1e-15f);
        float ftv[16];
        float fn2 = 0.f;
#pragma unroll
        for (int i = 0; i < 16; i++) {
            ftv[i] = (c1 * mv[i] + c2 * bb[i]) * iden;
            fn2 += ftv[i] * ftv[i];
        }
        fn2 = red16(fn2);
        float yn = sqrtf(fmaxf(fn2, 1e-30f));
        float lm = atanhf(fminf(yn, 0.9999999f)) / yn;
        float q0 = 0.f, q1 = 0.f;
        float elv[16];
#pragma unroll
        for (int i = 0; i < 16; i++) {
            elv[i] = lm * ftv[i];
            if (i < 8) q0 += elv[i] * at[i];
            else       q1 += elv[i] * at[i];
        }
        q0 = red16(q0);
        q1 = red16(q1);
        if (row < nrows) {
#pragma unroll
            for (int j = 0; j < 4; j++) {
                *(float4*)&feat_out[(size_t)row * HD + j * 64 + tx * 4] =
                    make_float4(ftv[j * 4 + 0], ftv[j * 4 + 1], ftv[j * 4 + 2], ftv[j * 4 + 3]);
            }
            if (el_out) {
#pragma unroll
                for (int j = 0; j < 4; j++) {
                    *(float4*)&el_out[(size_t)row * HD + j * 64 + tx * 4] =
                        make_float4(elv[j * 4 + 0], elv[j * 4 + 1], elv[j * 4 + 2], elv[j * 4 + 3]);
                }
            }
            if (tx == 0) {
                n2_out[row] = fn2;
                q_out[row * 2 + 0] = q0;
                q_out[row * 2 + 1] = q1;
            }
        }
    }
}

// ---------------- edge pass A: dot / ball_dist / e logits / segment max(inv) ----------------
__global__ void edgeA(const int* __restrict__ src_idx, const int* __restrict__ dst_idx) {
    int gid = blockIdx.x * blockDim.x + threadIdx.x;
    int e = gid >> 5, lane = gid & 31;
    if (e >= N_EDGE) return;
    int s = src_idx[e], t = dst_idx[e];
    const float4* fs = (const float4*)(g_feat_src + (size_t)s * HD);
    const float4* fd = (const float4*)(g_feat_dst + (size_t)t * HD);
    float4 a0 = fs[lane], b0 = fd[lane];
    float4 a1 = fs[lane + 32], b1 = fd[lane + 32];
    float xy = a0.x * b0.x + a0.y * b0.y + a0.z * b0.z + a0.w * b0.w +
               a1.x * b1.x + a1.y * b1.y + a1.z * b1.z + a1.w * b1.w;
    xy = red32(xy);
    if (lane == 0) {
        float x2 = g_x2[s], y2 = g_y2[t];
        float A = 1.f - 2.f * xy + y2;
        float B = 1.f - x2;
        float num2 = A * A * x2 - 2.f * A * B * xy + B * B * y2;
        float den = fmaxf(1.f - 2.f * xy + x2 * y2, 1e-15f);
        float nn = sqrtf(fmaxf(num2 / (den * den), 1e-30f));
        float dist = 2.f * atanhf(fminf(nn, 0.9999999f));
        float inv = 1.f / (1e-15f + dist);
        g_inv[e] = inv;
        g_e[e * 2 + 0] = g_qs[s * 2 + 0] + g_qr[t * 2 + 0];
        g_e[e * 2 + 1] = g_qs[s * 2 + 1] + g_qr[t * 2 + 1];
        atomicMax(&g_m1[t], fenc(inv));
    }
}

// ---------------- edge pass B: z1 = exp(inv - m1), segment sum ----------------
__global__ void edgeB(const int* __restrict__ dst_idx) {
    int e = blockIdx.x * blockDim.x + threadIdx.x;
    if (e >= N_EDGE) return;
    int t = dst_idx[e];
    float z = expf(g_inv[e] - fdec(g_m1[t]));
    g_z1[e] = z;
    atomicAdd(&g_s1[t], z);
}

// ---------------- edge pass C: dsm, leaky_relu(e*dsm), segment max ----------------
__global__ void edgeC(const int* __restrict__ dst_idx) {
    int e = blockIdx.x * blockDim.x + threadIdx.x;
    if (e >= N_EDGE) return;
    int t = dst_idx[e];
    float dsm = g_z1[e] / g_s1[t];
#pragma unroll
    for (int h = 0; h < 2; h++) {
        float v = g_e[e * 2 + h] * dsm;
        v = (v > 0.f) ? v : 0.2f * v;
        g_e2[e * 2 + h] = v;
        atomicMax(&g_m2[t * 2 + h], fenc(v));
    }
}

// ---------------- edge pass D: z2 = exp(e2 - m2), segment sum ----------------
__global__ void edgeD(const int* __restrict__ dst_idx) {
    int e = blockIdx.x * blockDim.x + threadIdx.x;
    if (e >= N_EDGE) return;
    int t = dst_idx[e];
#pragma unroll
    for (int h = 0; h < 2; h++) {
        float z = expf(g_e2[e * 2 + h] - fdec(g_m2[t * 2 + h]));
        g_z2[e * 2 + h] = z;
        atomicAdd(&g_s2[t * 2 + h], z);
    }
}

// ---------------- edge pass E: ft += el[src] * a (vector red) ----------------
__global__ void edgeE(const int* __restrict__ src_idx, const int* __restrict__ dst_idx,
                      float* __restrict__ out) {
    int gid = blockIdx.x * blockDim.x + threadIdx.x;
    int e = gid >> 5, lane = gid & 31;
    if (e >= N_EDGE) return;
    int s = src_idx[e], t = dst_idx[e];
    float a0 = g_z2[e * 2 + 0] / g_s2[t * 2 + 0];
    float a1 = g_z2[e * 2 + 1] / g_s2[t * 2 + 1];
    const float4* el = (const float4*)(g_el + (size_t)s * HD);
    float4 v0 = el[lane];       // head 0
    float4 v1 = el[lane + 32];  // head 1
    float* o = out + (size_t)t * HD + lane * 4;
    asm volatile("red.global.add.v4.f32 [%0], {%1, %2, %3, %4};"
                 :: "l"(o), "f"(v0.x * a0), "f"(v0.y * a0), "f"(v0.z * a0), "f"(v0.w * a0)
                 : "memory");
    asm volatile("red.global.add.v4.f32 [%0], {%1, %2, %3, %4};"
                 :: "l"(o + 128), "f"(v1.x * a1), "f"(v1.y * a1), "f"(v1.z * a1), "f"(v1.w * a1)
                 : "memory");
}

// ---------------- finalize: out = expmap0(out) in place ----------------
__global__ void finalize(float* __restrict__ out) {
    int gid = blockIdx.x * blockDim.x + threadIdx.x;
    int r = gid >> 5, lane = gid & 31;
    if (r >= N_DST) return;
    float4* o = (float4*)(out + (size_t)r * HD);
    float4 u0 = o[lane], u1 = o[lane + 32];
    float s = u0.x * u0.x + u0.y * u0.y + u0.z * u0.z + u0.w * u0.w +
              u1.x * u1.x + u1.y * u1.y + u1.z * u1.z + u1.w * u1.w;
    s = red32(s);
    float un = sqrtf(fmaxf(s, 1e-30f));
    float sc = tanhf(un) / un;
    u0.x *= sc; u0.y *= sc; u0.z *= sc; u0.w *= sc;
    u1.x *= sc; u1.y *= sc; u1.z *= sc; u1.w *= sc;
    o[lane] = u0;
    o[lane + 32] = u1;
}

// ---------------- launch ----------------
extern "C" void kernel_launch(void* const* d_in, const int* in_sizes, int n_in,
                              void* d_out, int out_size) {
    const float* hyper  = (const float*)d_in[0];
    const float* dt     = (const float*)d_in[1];
    const float* time_w = (const float*)d_in[2];
    const float* time_b = (const float*)d_in[3];
    const float* w_src  = (const float*)d_in[4];
    const float* b_src  = (const float*)d_in[5];
    const float* w_dst  = (const float*)d_in[6];
    const float* b_dst  = (const float*)d_in[7];
    const float* attn   = (const float*)d_in[8];
    const int* src_idx  = (const int*)d_in[9];
    const int* dst_idx  = (const int*)d_in[10];
    float* out = (float*)d_out;

    (void)in_sizes; (void)n_in; (void)out_size;

    init_kernel<<<512, 256>>>(out);
    prep_w<<<(DIM * HD + 255) / 256, 256>>>(w_src, w_dst);
    bias_norm<<<2, 256>>>(b_src, b_dst);
    node_prep<<<(N_TOT * 32 + 255) / 256, 256>>>(hyper, dt, time_w, time_b);

    const int SMEM = (DIM * HD + 64 * DIM) * (int)sizeof(float);  // 160 KB
    cudaFuncSetAttribute(gemm_epi, cudaFuncAttributeMaxDynamicSharedMemorySize, SMEM);
    gemm_epi<<<(N_TOT + 63) / 64, 256, SMEM>>>(b_src, attn, N_TOT, 0);
    gemm_epi<<<(N_DST + 63) / 64, 256, SMEM>>>(b_dst, attn, N_DST, 1);

    int eb = (N_EDGE * 32 + 255) / 256;   // warp-per-edge kernels
    int sb = (N_EDGE + 255) / 256;        // thread-per-edge kernels
    edgeA<<<eb, 256>>>(src_idx, dst_idx);
    edgeB<<<sb, 256>>>(dst_idx);
    edgeC<<<sb, 256>>>(dst_idx);
    edgeD<<<sb, 256>>>(dst_idx);
    edgeE<<<eb, 256>>>(src_idx, dst_idx, out);
    finalize<<<(N_DST * 32 + 255) / 256, 256>>>(out);
}